// round 1
// baseline (speedup 1.0000x reference)
#include <cuda_runtime.h>
#include <math.h>

// ---------------- problem constants ----------------
#define D_NUMF   24
#define N_FREQ   16
#define D_EMB    32
#define D_IN     32
#define D_FEAT   776      // 24*32 + 8
#define DIM      512
#define D_OUT    10
#define NX       1024
#define NC       100000

// ---------------- tiling constants ----------------
#define ENC_M    32       // rows per encode block
#define ENC_DC   128      // d-chunk (output cols per pass)
#define ENC_KC   128      // k-chunk staged in smem
#define WS_STR   132      // padded stride for w chunk (conflict-free LDS.128)

#define XT       32       // x rows per nca block
#define CT       64       // candidate chunk
#define SPLITS   50
#define SPLIT_LEN 2000    // NC / SPLITS
#define CS_STR   516      // padded strides (516 mod 32 == 4 -> conflict-free)
#define XS_STR   516

// ---------------- device scratch (alloc-free) ----------------
__device__ float g_ce[NC * DIM];     // candidate embeddings
__device__ float g_cn[NC];           // candidate sq-norms
__device__ float g_xe[NX * DIM];     // x embeddings
__device__ float g_xn[NX];           // x sq-norms
__device__ float g_part[NX * SPLITS * (D_OUT + 1)];  // per-split partials: [l, num0..9]

// =====================================================================
// Kernel 1: encode (shared by candidates and x; block id selects source)
// =====================================================================
__global__ void __launch_bounds__(256, 1)
encode_kernel(const float* __restrict__ cx, const float* __restrict__ xx,
              const float* __restrict__ freq, const float* __restrict__ plr_w,
              const float* __restrict__ plr_b, const float* __restrict__ enc_w,
              const float* __restrict__ enc_b)
{
    extern __shared__ float smem[];
    float* feat = smem;                    // ENC_M * D_FEAT
    float* wbuf = smem + ENC_M * D_FEAT;   // ENC_DC * WS_STR

    __shared__ float s_freq[D_NUMF * N_FREQ];
    __shared__ float s_pw[D_EMB * 2 * N_FREQ];
    __shared__ float s_pb[D_EMB];

    const int tid = threadIdx.x;
    const int nCandBlocks = NC / ENC_M;          // 3125
    const bool isX = (blockIdx.x >= nCandBlocks);
    const float* __restrict__ src = isX ? xx : cx;
    float* __restrict__ dstE = isX ? g_xe : g_ce;
    float* __restrict__ dstN = isX ? g_xn : g_cn;
    const int rowBase = (isX ? (int)blockIdx.x - nCandBlocks : (int)blockIdx.x) * ENC_M;

    for (int i = tid; i < D_NUMF * N_FREQ; i += 256) s_freq[i] = freq[i];
    for (int i = tid; i < D_EMB * 2 * N_FREQ; i += 256) s_pw[i] = plr_w[i];
    if (tid < D_EMB) s_pb[tid] = plr_b[tid];
    __syncthreads();

    // ---- stage 1: PLR features into smem ----
    for (int p = tid; p < ENC_M * D_NUMF; p += 256) {
        const int row = p / D_NUMF;
        const int n   = p % D_NUMF;
        const float vn = src[(rowBase + row) * D_IN + n];
        float zc[N_FREQ], zs[N_FREQ];
#pragma unroll
        for (int f = 0; f < N_FREQ; f++) {
            float th = 6.283185307179586f * s_freq[n * N_FREQ + f] * vn;
            __sincosf(th, &zs[f], &zc[f]);
        }
        float* fr = feat + row * D_FEAT + n * D_EMB;
#pragma unroll 4
        for (int e = 0; e < D_EMB; e++) {
            float acc = s_pb[e];
#pragma unroll
            for (int f = 0; f < N_FREQ; f++) {
                acc += zc[f] * s_pw[e * 32 + f];
                acc += zs[f] * s_pw[e * 32 + 16 + f];
            }
            fr[e] = fmaxf(acc, 0.0f);
        }
    }
    if (tid < ENC_M * (D_IN - D_NUMF)) {
        const int row = tid / (D_IN - D_NUMF);
        const int c   = tid % (D_IN - D_NUMF);
        feat[row * D_FEAT + D_NUMF * D_EMB + c] = src[(rowBase + row) * D_IN + D_NUMF + c];
    }
    __syncthreads();

    // ---- stage 2: feat(32x776) @ enc_w^T(776x512) ----
    const int tm = tid >> 5;   // 0..7 -> rows 4*tm..4*tm+3
    const int tn = tid & 31;   // 0..31 -> cols tn + 32*j
    float rowsq[4] = {0.f, 0.f, 0.f, 0.f};

    for (int dc = 0; dc < DIM; dc += ENC_DC) {
        float acc[4][4];
#pragma unroll
        for (int j = 0; j < 4; j++) {
            const float b = enc_b[dc + tn + 32 * j];
#pragma unroll
            for (int i = 0; i < 4; i++) acc[i][j] = b;
        }

        for (int kb = 0; kb < D_FEAT; kb += ENC_KC) {
            const int kl = min(ENC_KC, D_FEAT - kb);   // 128 ... last = 8
            __syncthreads();
            // cooperative, coalesced stage of enc_w chunk
            const int tot4 = ENC_DC * (kl >> 2);
            for (int lin = tid; lin < tot4; lin += 256) {
                const int dd = lin / (kl >> 2);
                const int k4 = lin % (kl >> 2);
                const float4 wv = *(const float4*)(enc_w + (size_t)(dc + dd) * D_FEAT + kb + k4 * 4);
                *(float4*)(wbuf + dd * WS_STR + k4 * 4) = wv;
            }
            __syncthreads();

            for (int k = 0; k < kl; k += 4) {
                float4 fx[4], wv[4];
#pragma unroll
                for (int i = 0; i < 4; i++)
                    fx[i] = *(const float4*)(feat + (4 * tm + i) * D_FEAT + kb + k);
#pragma unroll
                for (int j = 0; j < 4; j++)
                    wv[j] = *(const float4*)(wbuf + (tn + 32 * j) * WS_STR + k);
#pragma unroll
                for (int i = 0; i < 4; i++) {
#pragma unroll
                    for (int j = 0; j < 4; j++) {
                        acc[i][j] += fx[i].x * wv[j].x;
                        acc[i][j] += fx[i].y * wv[j].y;
                        acc[i][j] += fx[i].z * wv[j].z;
                        acc[i][j] += fx[i].w * wv[j].w;
                    }
                }
            }
        }

#pragma unroll
        for (int i = 0; i < 4; i++) {
            const int row = rowBase + 4 * tm + i;
#pragma unroll
            for (int j = 0; j < 4; j++) {
                const int d = dc + tn + 32 * j;
                dstE[(size_t)row * DIM + d] = acc[i][j];
                rowsq[i] += acc[i][j] * acc[i][j];
            }
        }
    }

    // warp covers all 512 cols of its 4 rows -> warp reduce norms
#pragma unroll
    for (int i = 0; i < 4; i++) {
        float v = rowsq[i];
#pragma unroll
        for (int o = 16; o; o >>= 1) v += __shfl_xor_sync(0xffffffffu, v, o);
        if (tn == 0) dstN[rowBase + 4 * tm + i] = v;
    }
}

// =====================================================================
// Kernel 2: fused distance + softmax-accumulate + class aggregation
// grid: (NX/XT, SPLITS); x-tile fastest for L2 reuse of ce tiles
// =====================================================================
__global__ void __launch_bounds__(256, 1)
nca_kernel(const int* __restrict__ cy)
{
    extern __shared__ float smem[];
    float* xs = smem;                    // XT * XS_STR
    float* cs = smem + XT * XS_STR;      // CT * CS_STR
    __shared__ float s_cn[CT];
    __shared__ int   s_cy[CT];
    __shared__ float s_xn[XT];

    const int tid = threadIdx.x;
    const int tm = tid >> 5;   // rows 4*tm..4*tm+3
    const int tn = tid & 31;   // cols tn, tn+32
    const int xBase = blockIdx.x * XT;
    const int split = blockIdx.y;
    const int jBase0 = split * SPLIT_LEN;

    for (int lin = tid; lin < XT * (DIM / 4); lin += 256) {
        const int r  = lin / (DIM / 4);
        const int k4 = lin % (DIM / 4);
        *(float4*)(xs + r * XS_STR + k4 * 4) =
            *(const float4*)(g_xe + (size_t)(xBase + r) * DIM + k4 * 4);
    }
    if (tid < XT) s_xn[tid] = g_xn[xBase + tid];
    __syncthreads();

    float xn[4];
#pragma unroll
    for (int i = 0; i < 4; i++) xn[i] = s_xn[4 * tm + i];

    float l[4] = {0.f, 0.f, 0.f, 0.f};
    float num[4][D_OUT];
#pragma unroll
    for (int i = 0; i < 4; i++)
#pragma unroll
        for (int c = 0; c < D_OUT; c++) num[i][c] = 0.f;

    for (int jb = 0; jb < SPLIT_LEN; jb += CT) {
        __syncthreads();   // protect cs/s_cn/s_cy reuse
        const int nj = min(CT, SPLIT_LEN - jb);

        for (int lin = tid; lin < CT * (DIM / 4); lin += 256) {
            const int r  = lin / (DIM / 4);
            const int k4 = lin % (DIM / 4);
            float4 v = make_float4(0.f, 0.f, 0.f, 0.f);
            if (r < nj) v = *(const float4*)(g_ce + (size_t)(jBase0 + jb + r) * DIM + k4 * 4);
            *(float4*)(cs + r * CS_STR + k4 * 4) = v;
        }
        if (tid < CT) {
            const bool ok = tid < nj;
            s_cn[tid] = ok ? g_cn[jBase0 + jb + tid] : 0.f;
            s_cy[tid] = ok ? cy[jBase0 + jb + tid] : 0;
        }
        __syncthreads();

        float acc[4][2];
#pragma unroll
        for (int i = 0; i < 4; i++) { acc[i][0] = 0.f; acc[i][1] = 0.f; }

        for (int k = 0; k < DIM; k += 4) {
            float4 fx[4], fc[2];
#pragma unroll
            for (int i = 0; i < 4; i++)
                fx[i] = *(const float4*)(xs + (4 * tm + i) * XS_STR + k);
#pragma unroll
            for (int j = 0; j < 2; j++)
                fc[j] = *(const float4*)(cs + (tn + 32 * j) * CS_STR + k);
#pragma unroll
            for (int i = 0; i < 4; i++) {
#pragma unroll
                for (int j = 0; j < 2; j++) {
                    acc[i][j] += fx[i].x * fc[j].x;
                    acc[i][j] += fx[i].y * fc[j].y;
                    acc[i][j] += fx[i].z * fc[j].z;
                    acc[i][j] += fx[i].w * fc[j].w;
                }
            }
        }

        // epilogue: exp(-dist), class-scatter via predicated adds (no max needed:
        // scores <= 0 so exp in (4e-18, 1], fp32-safe)
#pragma unroll
        for (int j = 0; j < 2; j++) {
            const int col = tn + 32 * j;
            if (col < nj) {
                const float cn = s_cn[col];
                const int   y  = s_cy[col];
#pragma unroll
                for (int i = 0; i < 4; i++) {
                    const float sq = xn[i] + cn - 2.f * acc[i][j];
                    const float d  = sqrtf(fmaxf(sq, 1e-12f));
                    const float e  = __expf(-d);
                    l[i] += e;
#pragma unroll
                    for (int c = 0; c < D_OUT; c++)
                        num[i][c] += (y == c) ? e : 0.f;
                }
            }
        }
    }

    // warp-level sums (all lanes of a warp share the same 4 rows)
#pragma unroll
    for (int i = 0; i < 4; i++) {
        float v = l[i];
#pragma unroll
        for (int o = 16; o; o >>= 1) v += __shfl_xor_sync(0xffffffffu, v, o);
        l[i] = v;
#pragma unroll
        for (int c = 0; c < D_OUT; c++) {
            float u = num[i][c];
#pragma unroll
            for (int o = 16; o; o >>= 1) u += __shfl_xor_sync(0xffffffffu, u, o);
            num[i][c] = u;
        }
    }
    if (tn == 0) {
#pragma unroll
        for (int i = 0; i < 4; i++) {
            const int row = xBase + 4 * tm + i;
            float* P = g_part + ((size_t)row * SPLITS + split) * (D_OUT + 1);
            P[0] = l[i];
#pragma unroll
            for (int c = 0; c < D_OUT; c++) P[1 + c] = num[i][c];
        }
    }
}

// =====================================================================
// Kernel 3: reduce split partials and write log-probs
// =====================================================================
__global__ void finalize_kernel(float* __restrict__ out)
{
    const int row = blockIdx.x * blockDim.x + threadIdx.x;
    if (row >= NX) return;
    float l = 0.f;
    float num[D_OUT];
#pragma unroll
    for (int c = 0; c < D_OUT; c++) num[c] = 0.f;
    const float* P = g_part + (size_t)row * SPLITS * (D_OUT + 1);
    for (int s = 0; s < SPLITS; s++) {
        l += P[s * (D_OUT + 1)];
#pragma unroll
        for (int c = 0; c < D_OUT; c++) num[c] += P[s * (D_OUT + 1) + 1 + c];
    }
    const float inv = 1.0f / l;
#pragma unroll
    for (int c = 0; c < D_OUT; c++)
        out[row * D_OUT + c] = logf(num[c] * inv + 1e-7f);
}

// =====================================================================
extern "C" void kernel_launch(void* const* d_in, const int* in_sizes, int n_in,
                              void* d_out, int out_size)
{
    const float* x     = (const float*)d_in[0];
    const float* cx    = (const float*)d_in[1];
    const int*   cy    = (const int*)d_in[2];
    const float* freq  = (const float*)d_in[3];
    const float* plr_w = (const float*)d_in[4];
    const float* plr_b = (const float*)d_in[5];
    const float* enc_w = (const float*)d_in[6];
    const float* enc_b = (const float*)d_in[7];
    float* out = (float*)d_out;

    const size_t encSmem = (size_t)(ENC_M * D_FEAT + ENC_DC * WS_STR) * sizeof(float); // 166912
    const size_t ncaSmem = (size_t)(XT * XS_STR + CT * CS_STR) * sizeof(float);        // 198144
    cudaFuncSetAttribute(encode_kernel, cudaFuncAttributeMaxDynamicSharedMemorySize, (int)encSmem);
    cudaFuncSetAttribute(nca_kernel,    cudaFuncAttributeMaxDynamicSharedMemorySize, (int)ncaSmem);

    const int encBlocks = NC / ENC_M + NX / ENC_M;   // 3125 + 32
    encode_kernel<<<encBlocks, 256, encSmem>>>(cx, x, freq, plr_w, plr_b, enc_w, enc_b);

    dim3 g2(NX / XT, SPLITS);                         // (32, 50), x fastest for L2 reuse
    nca_kernel<<<g2, 256, ncaSmem>>>(cy);

    finalize_kernel<<<(NX + 255) / 256, 256>>>(out);
}

// round 2
// speedup vs baseline: 1.0041x; 1.0041x over previous
#include <cuda_runtime.h>
#include <math.h>

// ---------------- problem constants ----------------
#define D_NUMF   24
#define N_FREQ   16
#define D_EMB    32
#define D_IN     32
#define D_FEAT   776      // 24*32 + 8
#define DIM      512
#define D_OUT    10
#define NX       1024
#define NC       100000

// ---------------- tiling constants ----------------
#define ENC_M    32       // rows per encode block
#define ENC_DC   128      // d-chunk (output cols per pass)
#define ENC_KC   128      // k-chunk staged in smem
#define WS_STR   132      // padded stride for w chunk (conflict-free LDS.128)

#define XT       32       // x rows per nca block
#define CT       64       // candidate chunk
#define SPLITS   50
#define SPLIT_LEN 2000    // NC / SPLITS
#define CS_STR   516      // padded strides (516 mod 32 == 4 -> conflict-free)
#define XS_STR   516

// ---------------- device scratch (alloc-free) ----------------
__device__ float g_ce[NC * DIM];     // candidate embeddings
__device__ float g_cn[NC];           // candidate sq-norms
__device__ float g_xe[NX * DIM];     // x embeddings
__device__ float g_xn[NX];           // x sq-norms
__device__ float g_part[NX * SPLITS * (D_OUT + 1)];  // per-split partials: [l, num0..9]

// =====================================================================
// Kernel 1: encode (shared by candidates and x; block id selects source)
// =====================================================================
__global__ void __launch_bounds__(256, 1)
encode_kernel(const float* __restrict__ cx, const float* __restrict__ xx,
              const float* __restrict__ freq, const float* __restrict__ plr_w,
              const float* __restrict__ plr_b, const float* __restrict__ enc_w,
              const float* __restrict__ enc_b)
{
    extern __shared__ float smem[];
    float* feat = smem;                    // ENC_M * D_FEAT
    float* wbuf = smem + ENC_M * D_FEAT;   // ENC_DC * WS_STR

    __shared__ float s_freq[D_NUMF * N_FREQ];
    __shared__ float s_pw[D_EMB * 2 * N_FREQ];
    __shared__ float s_pb[D_EMB];

    const int tid = threadIdx.x;
    const int nCandBlocks = NC / ENC_M;          // 3125
    const bool isX = (blockIdx.x >= nCandBlocks);
    const float* __restrict__ src = isX ? xx : cx;
    float* __restrict__ dstE = isX ? g_xe : g_ce;
    float* __restrict__ dstN = isX ? g_xn : g_cn;
    const int rowBase = (isX ? (int)blockIdx.x - nCandBlocks : (int)blockIdx.x) * ENC_M;

    for (int i = tid; i < D_NUMF * N_FREQ; i += 256) s_freq[i] = freq[i];
    for (int i = tid; i < D_EMB * 2 * N_FREQ; i += 256) s_pw[i] = plr_w[i];
    if (tid < D_EMB) s_pb[tid] = plr_b[tid];
    __syncthreads();

    // ---- stage 1: PLR features into smem ----
    for (int p = tid; p < ENC_M * D_NUMF; p += 256) {
        const int row = p / D_NUMF;
        const int n   = p % D_NUMF;
        const float vn = src[(rowBase + row) * D_IN + n];
        float zc[N_FREQ], zs[N_FREQ];
#pragma unroll
        for (int f = 0; f < N_FREQ; f++) {
            float th = 6.283185307179586f * s_freq[n * N_FREQ + f] * vn;
            __sincosf(th, &zs[f], &zc[f]);
        }
        float* fr = feat + row * D_FEAT + n * D_EMB;
#pragma unroll 4
        for (int e = 0; e < D_EMB; e++) {
            float acc = s_pb[e];
#pragma unroll
            for (int f = 0; f < N_FREQ; f++) {
                acc += zc[f] * s_pw[e * 32 + f];
                acc += zs[f] * s_pw[e * 32 + 16 + f];
            }
            fr[e] = fmaxf(acc, 0.0f);
        }
    }
    if (tid < ENC_M * (D_IN - D_NUMF)) {
        const int row = tid / (D_IN - D_NUMF);
        const int c   = tid % (D_IN - D_NUMF);
        feat[row * D_FEAT + D_NUMF * D_EMB + c] = src[(rowBase + row) * D_IN + D_NUMF + c];
    }
    __syncthreads();

    // ---- stage 2: feat(32x776) @ enc_w^T(776x512) ----
    const int tm = tid >> 5;   // 0..7 -> rows 4*tm..4*tm+3
    const int tn = tid & 31;   // 0..31 -> cols tn + 32*j
    float rowsq[4] = {0.f, 0.f, 0.f, 0.f};

    for (int dc = 0; dc < DIM; dc += ENC_DC) {
        float acc[4][4];
#pragma unroll
        for (int j = 0; j < 4; j++) {
            const float b = enc_b[dc + tn + 32 * j];
#pragma unroll
            for (int i = 0; i < 4; i++) acc[i][j] = b;
        }

        for (int kb = 0; kb < D_FEAT; kb += ENC_KC) {
            const int kl = min(ENC_KC, D_FEAT - kb);   // 128 ... last = 8
            __syncthreads();
            // cooperative, coalesced stage of enc_w chunk
            const int tot4 = ENC_DC * (kl >> 2);
            for (int lin = tid; lin < tot4; lin += 256) {
                const int dd = lin / (kl >> 2);
                const int k4 = lin % (kl >> 2);
                const float4 wv = *(const float4*)(enc_w + (size_t)(dc + dd) * D_FEAT + kb + k4 * 4);
                *(float4*)(wbuf + dd * WS_STR + k4 * 4) = wv;
            }
            __syncthreads();

            for (int k = 0; k < kl; k += 4) {
                float4 fx[4], wv[4];
#pragma unroll
                for (int i = 0; i < 4; i++)
                    fx[i] = *(const float4*)(feat + (4 * tm + i) * D_FEAT + kb + k);
#pragma unroll
                for (int j = 0; j < 4; j++)
                    wv[j] = *(const float4*)(wbuf + (tn + 32 * j) * WS_STR + k);
#pragma unroll
                for (int i = 0; i < 4; i++) {
#pragma unroll
                    for (int j = 0; j < 4; j++) {
                        acc[i][j] += fx[i].x * wv[j].x;
                        acc[i][j] += fx[i].y * wv[j].y;
                        acc[i][j] += fx[i].z * wv[j].z;
                        acc[i][j] += fx[i].w * wv[j].w;
                    }
                }
            }
        }

#pragma unroll
        for (int i = 0; i < 4; i++) {
            const int row = rowBase + 4 * tm + i;
#pragma unroll
            for (int j = 0; j < 4; j++) {
                const int d = dc + tn + 32 * j;
                dstE[(size_t)row * DIM + d] = acc[i][j];
                rowsq[i] += acc[i][j] * acc[i][j];
            }
        }
    }

    // warp covers all 512 cols of its 4 rows -> warp reduce norms
#pragma unroll
    for (int i = 0; i < 4; i++) {
        float v = rowsq[i];
#pragma unroll
        for (int o = 16; o; o >>= 1) v += __shfl_xor_sync(0xffffffffu, v, o);
        if (tn == 0) dstN[rowBase + 4 * tm + i] = v;
    }
}

// =====================================================================
// Kernel 2: fused distance + softmax-accumulate + class aggregation
// grid: (NX/XT, SPLITS); x-tile fastest for L2 reuse of ce tiles
// =====================================================================
__global__ void __launch_bounds__(256, 1)
nca_kernel(const int* __restrict__ cy)
{
    extern __shared__ float smem[];
    float* xs = smem;                    // XT * XS_STR
    float* cs = smem + XT * XS_STR;      // CT * CS_STR
    __shared__ float s_cn[CT];
    __shared__ int   s_cy[CT];
    __shared__ float s_xn[XT];

    const int tid = threadIdx.x;
    const int tm = tid >> 5;   // rows 4*tm..4*tm+3
    const int tn = tid & 31;   // cols tn, tn+32
    const int xBase = blockIdx.x * XT;
    const int split = blockIdx.y;
    const int jBase0 = split * SPLIT_LEN;

    for (int lin = tid; lin < XT * (DIM / 4); lin += 256) {
        const int r  = lin / (DIM / 4);
        const int k4 = lin % (DIM / 4);
        *(float4*)(xs + r * XS_STR + k4 * 4) =
            *(const float4*)(g_xe + (size_t)(xBase + r) * DIM + k4 * 4);
    }
    if (tid < XT) s_xn[tid] = g_xn[xBase + tid];
    __syncthreads();

    float xn[4];
#pragma unroll
    for (int i = 0; i < 4; i++) xn[i] = s_xn[4 * tm + i];

    float l[4] = {0.f, 0.f, 0.f, 0.f};
    float num[4][D_OUT];
#pragma unroll
    for (int i = 0; i < 4; i++)
#pragma unroll
        for (int c = 0; c < D_OUT; c++) num[i][c] = 0.f;

    for (int jb = 0; jb < SPLIT_LEN; jb += CT) {
        __syncthreads();   // protect cs/s_cn/s_cy reuse
        const int nj = min(CT, SPLIT_LEN - jb);

        for (int lin = tid; lin < CT * (DIM / 4); lin += 256) {
            const int r  = lin / (DIM / 4);
            const int k4 = lin % (DIM / 4);
            float4 v = make_float4(0.f, 0.f, 0.f, 0.f);
            if (r < nj) v = *(const float4*)(g_ce + (size_t)(jBase0 + jb + r) * DIM + k4 * 4);
            *(float4*)(cs + r * CS_STR + k4 * 4) = v;
        }
        if (tid < CT) {
            const bool ok = tid < nj;
            s_cn[tid] = ok ? g_cn[jBase0 + jb + tid] : 0.f;
            s_cy[tid] = ok ? cy[jBase0 + jb + tid] : 0;
        }
        __syncthreads();

        float acc[4][2];
#pragma unroll
        for (int i = 0; i < 4; i++) { acc[i][0] = 0.f; acc[i][1] = 0.f; }

        for (int k = 0; k < DIM; k += 4) {
            float4 fx[4], fc[2];
#pragma unroll
            for (int i = 0; i < 4; i++)
                fx[i] = *(const float4*)(xs + (4 * tm + i) * XS_STR + k);
#pragma unroll
            for (int j = 0; j < 2; j++)
                fc[j] = *(const float4*)(cs + (tn + 32 * j) * CS_STR + k);
#pragma unroll
            for (int i = 0; i < 4; i++) {
#pragma unroll
                for (int j = 0; j < 2; j++) {
                    acc[i][j] += fx[i].x * fc[j].x;
                    acc[i][j] += fx[i].y * fc[j].y;
                    acc[i][j] += fx[i].z * fc[j].z;
                    acc[i][j] += fx[i].w * fc[j].w;
                }
            }
        }

        // epilogue: exp(-dist), class-scatter via predicated adds (no max needed:
        // scores <= 0 so exp in (4e-18, 1], fp32-safe)
#pragma unroll
        for (int j = 0; j < 2; j++) {
            const int col = tn + 32 * j;
            if (col < nj) {
                const float cn = s_cn[col];
                const int   y  = s_cy[col];
#pragma unroll
                for (int i = 0; i < 4; i++) {
                    const float sq = xn[i] + cn - 2.f * acc[i][j];
                    const float d  = sqrtf(fmaxf(sq, 1e-12f));
                    const float e  = __expf(-d);
                    l[i] += e;
#pragma unroll
                    for (int c = 0; c < D_OUT; c++)
                        num[i][c] += (y == c) ? e : 0.f;
                }
            }
        }
    }

    // warp-level sums (all lanes of a warp share the same 4 rows)
#pragma unroll
    for (int i = 0; i < 4; i++) {
        float v = l[i];
#pragma unroll
        for (int o = 16; o; o >>= 1) v += __shfl_xor_sync(0xffffffffu, v, o);
        l[i] = v;
#pragma unroll
        for (int c = 0; c < D_OUT; c++) {
            float u = num[i][c];
#pragma unroll
            for (int o = 16; o; o >>= 1) u += __shfl_xor_sync(0xffffffffu, u, o);
            num[i][c] = u;
        }
    }
    if (tn == 0) {
#pragma unroll
        for (int i = 0; i < 4; i++) {
            const int row = xBase + 4 * tm + i;
            float* P = g_part + ((size_t)row * SPLITS + split) * (D_OUT + 1);
            P[0] = l[i];
#pragma unroll
            for (int c = 0; c < D_OUT; c++) P[1 + c] = num[i][c];
        }
    }
}

// =====================================================================
// Kernel 3: reduce split partials and write log-probs
// =====================================================================
__global__ void finalize_kernel(float* __restrict__ out)
{
    const int row = blockIdx.x * blockDim.x + threadIdx.x;
    if (row >= NX) return;
    float l = 0.f;
    float num[D_OUT];
#pragma unroll
    for (int c = 0; c < D_OUT; c++) num[c] = 0.f;
    const float* P = g_part + (size_t)row * SPLITS * (D_OUT + 1);
    for (int s = 0; s < SPLITS; s++) {
        l += P[s * (D_OUT + 1)];
#pragma unroll
        for (int c = 0; c < D_OUT; c++) num[c] += P[s * (D_OUT + 1) + 1 + c];
    }
    const float inv = 1.0f / l;
#pragma unroll
    for (int c = 0; c < D_OUT; c++)
        out[row * D_OUT + c] = logf(num[c] * inv + 1e-7f);
}

// =====================================================================
extern "C" void kernel_launch(void* const* d_in, const int* in_sizes, int n_in,
                              void* d_out, int out_size)
{
    const float* x     = (const float*)d_in[0];
    const float* cx    = (const float*)d_in[1];
    const int*   cy    = (const int*)d_in[2];
    const float* freq  = (const float*)d_in[3];
    const float* plr_w = (const float*)d_in[4];
    const float* plr_b = (const float*)d_in[5];
    const float* enc_w = (const float*)d_in[6];
    const float* enc_b = (const float*)d_in[7];
    float* out = (float*)d_out;

    const size_t encSmem = (size_t)(ENC_M * D_FEAT + ENC_DC * WS_STR) * sizeof(float); // 166912
    const size_t ncaSmem = (size_t)(XT * XS_STR + CT * CS_STR) * sizeof(float);        // 198144
    cudaFuncSetAttribute(encode_kernel, cudaFuncAttributeMaxDynamicSharedMemorySize, (int)encSmem);
    cudaFuncSetAttribute(nca_kernel,    cudaFuncAttributeMaxDynamicSharedMemorySize, (int)ncaSmem);

    const int encBlocks = NC / ENC_M + NX / ENC_M;   // 3125 + 32
    encode_kernel<<<encBlocks, 256, encSmem>>>(cx, x, freq, plr_w, plr_b, enc_w, enc_b);

    dim3 g2(NX / XT, SPLITS);                         // (32, 50), x fastest for L2 reuse
    nca_kernel<<<g2, 256, ncaSmem>>>(cy);

    finalize_kernel<<<(NX + 255) / 256, 256>>>(out);
}

// round 3
// speedup vs baseline: 1.0048x; 1.0007x over previous
#include <cuda_runtime.h>
#include <math.h>

// ---------------- problem constants ----------------
#define D_NUMF   24
#define N_FREQ   16
#define D_EMB    32
#define D_IN     32
#define D_FEAT   776      // 24*32 + 8
#define DIM      512
#define D_OUT    10
#define NX       1024
#define NC       100000

// ---------------- tiling constants ----------------
#define ENC_M    32       // rows per encode block
#define ENC_DC   128      // d-chunk (output cols per pass)
#define ENC_KC   128      // k-chunk staged in smem
#define WS_STR   132      // padded stride for w chunk (conflict-free LDS.128)

#define XT       32       // x rows per nca block
#define CT       64       // candidate chunk
#define SPLITS   50
#define SPLIT_LEN 2000    // NC / SPLITS
#define CS_STR   516      // padded strides (516 mod 32 == 4 -> conflict-free)
#define XS_STR   516

// ---------------- device scratch (alloc-free) ----------------
__device__ float g_ce[NC * DIM];     // candidate embeddings
__device__ float g_cn[NC];           // candidate sq-norms
__device__ float g_xe[NX * DIM];     // x embeddings
__device__ float g_xn[NX];           // x sq-norms
__device__ float g_part[NX * SPLITS * (D_OUT + 1)];  // per-split partials: [l, num0..9]

// =====================================================================
// Kernel 1: encode (shared by candidates and x; block id selects source)
// =====================================================================
__global__ void __launch_bounds__(256, 1)
encode_kernel(const float* __restrict__ cx, const float* __restrict__ xx,
              const float* __restrict__ freq, const float* __restrict__ plr_w,
              const float* __restrict__ plr_b, const float* __restrict__ enc_w,
              const float* __restrict__ enc_b)
{
    extern __shared__ float smem[];
    float* feat = smem;                    // ENC_M * D_FEAT
    float* wbuf = smem + ENC_M * D_FEAT;   // ENC_DC * WS_STR

    __shared__ float s_freq[D_NUMF * N_FREQ];
    __shared__ float s_pw[D_EMB * 2 * N_FREQ];
    __shared__ float s_pb[D_EMB];

    const int tid = threadIdx.x;
    const int nCandBlocks = NC / ENC_M;          // 3125
    const bool isX = (blockIdx.x >= nCandBlocks);
    const float* __restrict__ src = isX ? xx : cx;
    float* __restrict__ dstE = isX ? g_xe : g_ce;
    float* __restrict__ dstN = isX ? g_xn : g_cn;
    const int rowBase = (isX ? (int)blockIdx.x - nCandBlocks : (int)blockIdx.x) * ENC_M;

    for (int i = tid; i < D_NUMF * N_FREQ; i += 256) s_freq[i] = freq[i];
    for (int i = tid; i < D_EMB * 2 * N_FREQ; i += 256) s_pw[i] = plr_w[i];
    if (tid < D_EMB) s_pb[tid] = plr_b[tid];
    __syncthreads();

    // ---- stage 1: PLR features into smem ----
    for (int p = tid; p < ENC_M * D_NUMF; p += 256) {
        const int row = p / D_NUMF;
        const int n   = p % D_NUMF;
        const float vn = src[(rowBase + row) * D_IN + n];
        float zc[N_FREQ], zs[N_FREQ];
#pragma unroll
        for (int f = 0; f < N_FREQ; f++) {
            float th = 6.283185307179586f * s_freq[n * N_FREQ + f] * vn;
            __sincosf(th, &zs[f], &zc[f]);
        }
        float* fr = feat + row * D_FEAT + n * D_EMB;
#pragma unroll 4
        for (int e = 0; e < D_EMB; e++) {
            float acc = s_pb[e];
#pragma unroll
            for (int f = 0; f < N_FREQ; f++) {
                acc += zc[f] * s_pw[e * 32 + f];
                acc += zs[f] * s_pw[e * 32 + 16 + f];
            }
            fr[e] = fmaxf(acc, 0.0f);
        }
    }
    if (tid < ENC_M * (D_IN - D_NUMF)) {
        const int row = tid / (D_IN - D_NUMF);
        const int c   = tid % (D_IN - D_NUMF);
        feat[row * D_FEAT + D_NUMF * D_EMB + c] = src[(rowBase + row) * D_IN + D_NUMF + c];
    }
    __syncthreads();

    // ---- stage 2: feat(32x776) @ enc_w^T(776x512) ----
    const int tm = tid >> 5;   // 0..7 -> rows 4*tm..4*tm+3
    const int tn = tid & 31;   // 0..31 -> cols tn + 32*j
    float rowsq[4] = {0.f, 0.f, 0.f, 0.f};

    for (int dc = 0; dc < DIM; dc += ENC_DC) {
        float acc[4][4];
#pragma unroll
        for (int j = 0; j < 4; j++) {
            const float b = enc_b[dc + tn + 32 * j];
#pragma unroll
            for (int i = 0; i < 4; i++) acc[i][j] = b;
        }

        for (int kb = 0; kb < D_FEAT; kb += ENC_KC) {
            const int kl = min(ENC_KC, D_FEAT - kb);   // 128 ... last = 8
            __syncthreads();
            // cooperative, coalesced stage of enc_w chunk
            const int tot4 = ENC_DC * (kl >> 2);
            for (int lin = tid; lin < tot4; lin += 256) {
                const int dd = lin / (kl >> 2);
                const int k4 = lin % (kl >> 2);
                const float4 wv = *(const float4*)(enc_w + (size_t)(dc + dd) * D_FEAT + kb + k4 * 4);
                *(float4*)(wbuf + dd * WS_STR + k4 * 4) = wv;
            }
            __syncthreads();

            for (int k = 0; k < kl; k += 4) {
                float4 fx[4], wv[4];
#pragma unroll
                for (int i = 0; i < 4; i++)
                    fx[i] = *(const float4*)(feat + (4 * tm + i) * D_FEAT + kb + k);
#pragma unroll
                for (int j = 0; j < 4; j++)
                    wv[j] = *(const float4*)(wbuf + (tn + 32 * j) * WS_STR + k);
#pragma unroll
                for (int i = 0; i < 4; i++) {
#pragma unroll
                    for (int j = 0; j < 4; j++) {
                        acc[i][j] += fx[i].x * wv[j].x;
                        acc[i][j] += fx[i].y * wv[j].y;
                        acc[i][j] += fx[i].z * wv[j].z;
                        acc[i][j] += fx[i].w * wv[j].w;
                    }
                }
            }
        }

#pragma unroll
        for (int i = 0; i < 4; i++) {
            const int row = rowBase + 4 * tm + i;
#pragma unroll
            for (int j = 0; j < 4; j++) {
                const int d = dc + tn + 32 * j;
                dstE[(size_t)row * DIM + d] = acc[i][j];
                rowsq[i] += acc[i][j] * acc[i][j];
            }
        }
    }

    // warp covers all 512 cols of its 4 rows -> warp reduce norms
#pragma unroll
    for (int i = 0; i < 4; i++) {
        float v = rowsq[i];
#pragma unroll
        for (int o = 16; o; o >>= 1) v += __shfl_xor_sync(0xffffffffu, v, o);
        if (tn == 0) dstN[rowBase + 4 * tm + i] = v;
    }
}

// =====================================================================
// Kernel 2: fused distance + softmax-accumulate + class aggregation
// grid: (NX/XT, SPLITS); x-tile fastest for L2 reuse of ce tiles
// =====================================================================
__global__ void __launch_bounds__(256, 1)
nca_kernel(const int* __restrict__ cy)
{
    extern __shared__ float smem[];
    float* xs = smem;                    // XT * XS_STR
    float* cs = smem + XT * XS_STR;      // CT * CS_STR
    __shared__ float s_cn[CT];
    __shared__ int   s_cy[CT];
    __shared__ float s_xn[XT];

    const int tid = threadIdx.x;
    const int tm = tid >> 5;   // rows 4*tm..4*tm+3
    const int tn = tid & 31;   // cols tn, tn+32
    const int xBase = blockIdx.x * XT;
    const int split = blockIdx.y;
    const int jBase0 = split * SPLIT_LEN;

    for (int lin = tid; lin < XT * (DIM / 4); lin += 256) {
        const int r  = lin / (DIM / 4);
        const int k4 = lin % (DIM / 4);
        *(float4*)(xs + r * XS_STR + k4 * 4) =
            *(const float4*)(g_xe + (size_t)(xBase + r) * DIM + k4 * 4);
    }
    if (tid < XT) s_xn[tid] = g_xn[xBase + tid];
    __syncthreads();

    float xn[4];
#pragma unroll
    for (int i = 0; i < 4; i++) xn[i] = s_xn[4 * tm + i];

    float l[4] = {0.f, 0.f, 0.f, 0.f};
    float num[4][D_OUT];
#pragma unroll
    for (int i = 0; i < 4; i++)
#pragma unroll
        for (int c = 0; c < D_OUT; c++) num[i][c] = 0.f;

    for (int jb = 0; jb < SPLIT_LEN; jb += CT) {
        __syncthreads();   // protect cs/s_cn/s_cy reuse
        const int nj = min(CT, SPLIT_LEN - jb);

        for (int lin = tid; lin < CT * (DIM / 4); lin += 256) {
            const int r  = lin / (DIM / 4);
            const int k4 = lin % (DIM / 4);
            float4 v = make_float4(0.f, 0.f, 0.f, 0.f);
            if (r < nj) v = *(const float4*)(g_ce + (size_t)(jBase0 + jb + r) * DIM + k4 * 4);
            *(float4*)(cs + r * CS_STR + k4 * 4) = v;
        }
        if (tid < CT) {
            const bool ok = tid < nj;
            s_cn[tid] = ok ? g_cn[jBase0 + jb + tid] : 0.f;
            s_cy[tid] = ok ? cy[jBase0 + jb + tid] : 0;
        }
        __syncthreads();

        float acc[4][2];
#pragma unroll
        for (int i = 0; i < 4; i++) { acc[i][0] = 0.f; acc[i][1] = 0.f; }

        for (int k = 0; k < DIM; k += 4) {
            float4 fx[4], fc[2];
#pragma unroll
            for (int i = 0; i < 4; i++)
                fx[i] = *(const float4*)(xs + (4 * tm + i) * XS_STR + k);
#pragma unroll
            for (int j = 0; j < 2; j++)
                fc[j] = *(const float4*)(cs + (tn + 32 * j) * CS_STR + k);
#pragma unroll
            for (int i = 0; i < 4; i++) {
#pragma unroll
                for (int j = 0; j < 2; j++) {
                    acc[i][j] += fx[i].x * fc[j].x;
                    acc[i][j] += fx[i].y * fc[j].y;
                    acc[i][j] += fx[i].z * fc[j].z;
                    acc[i][j] += fx[i].w * fc[j].w;
                }
            }
        }

        // epilogue: exp(-dist), class-scatter via predicated adds (no max needed:
        // scores <= 0 so exp in (4e-18, 1], fp32-safe)
#pragma unroll
        for (int j = 0; j < 2; j++) {
            const int col = tn + 32 * j;
            if (col < nj) {
                const float cn = s_cn[col];
                const int   y  = s_cy[col];
#pragma unroll
                for (int i = 0; i < 4; i++) {
                    const float sq = xn[i] + cn - 2.f * acc[i][j];
                    const float d  = sqrtf(fmaxf(sq, 1e-12f));
                    const float e  = __expf(-d);
                    l[i] += e;
#pragma unroll
                    for (int c = 0; c < D_OUT; c++)
                        num[i][c] += (y == c) ? e : 0.f;
                }
            }
        }
    }

    // warp-level sums (all lanes of a warp share the same 4 rows)
#pragma unroll
    for (int i = 0; i < 4; i++) {
        float v = l[i];
#pragma unroll
        for (int o = 16; o; o >>= 1) v += __shfl_xor_sync(0xffffffffu, v, o);
        l[i] = v;
#pragma unroll
        for (int c = 0; c < D_OUT; c++) {
            float u = num[i][c];
#pragma unroll
            for (int o = 16; o; o >>= 1) u += __shfl_xor_sync(0xffffffffu, u, o);
            num[i][c] = u;
        }
    }
    if (tn == 0) {
#pragma unroll
        for (int i = 0; i < 4; i++) {
            const int row = xBase + 4 * tm + i;
            float* P = g_part + ((size_t)row * SPLITS + split) * (D_OUT + 1);
            P[0] = l[i];
#pragma unroll
            for (int c = 0; c < D_OUT; c++) P[1 + c] = num[i][c];
        }
    }
}

// =====================================================================
// Kernel 3: reduce split partials and write log-probs
// =====================================================================
__global__ void finalize_kernel(float* __restrict__ out)
{
    const int row = blockIdx.x * blockDim.x + threadIdx.x;
    if (row >= NX) return;
    float l = 0.f;
    float num[D_OUT];
#pragma unroll
    for (int c = 0; c < D_OUT; c++) num[c] = 0.f;
    const float* P = g_part + (size_t)row * SPLITS * (D_OUT + 1);
    for (int s = 0; s < SPLITS; s++) {
        l += P[s * (D_OUT + 1)];
#pragma unroll
        for (int c = 0; c < D_OUT; c++) num[c] += P[s * (D_OUT + 1) + 1 + c];
    }
    const float inv = 1.0f / l;
#pragma unroll
    for (int c = 0; c < D_OUT; c++)
        out[row * D_OUT + c] = logf(num[c] * inv + 1e-7f);
}

// =====================================================================
extern "C" void kernel_launch(void* const* d_in, const int* in_sizes, int n_in,
                              void* d_out, int out_size)
{
    const float* x     = (const float*)d_in[0];
    const float* cx    = (const float*)d_in[1];
    const int*   cy    = (const int*)d_in[2];
    const float* freq  = (const float*)d_in[3];
    const float* plr_w = (const float*)d_in[4];
    const float* plr_b = (const float*)d_in[5];
    const float* enc_w = (const float*)d_in[6];
    const float* enc_b = (const float*)d_in[7];
    float* out = (float*)d_out;

    const size_t encSmem = (size_t)(ENC_M * D_FEAT + ENC_DC * WS_STR) * sizeof(float); // 166912
    const size_t ncaSmem = (size_t)(XT * XS_STR + CT * CS_STR) * sizeof(float);        // 198144
    cudaFuncSetAttribute(encode_kernel, cudaFuncAttributeMaxDynamicSharedMemorySize, (int)encSmem);
    cudaFuncSetAttribute(nca_kernel,    cudaFuncAttributeMaxDynamicSharedMemorySize, (int)ncaSmem);

    const int encBlocks = NC / ENC_M + NX / ENC_M;   // 3125 + 32
    encode_kernel<<<encBlocks, 256, encSmem>>>(cx, x, freq, plr_w, plr_b, enc_w, enc_b);

    dim3 g2(NX / XT, SPLITS);                         // (32, 50), x fastest for L2 reuse
    nca_kernel<<<g2, 256, ncaSmem>>>(cy);

    finalize_kernel<<<(NX + 255) / 256, 256>>>(out);
}

// round 4
// speedup vs baseline: 1.0057x; 1.0008x over previous
#include <cuda_runtime.h>
#include <math.h>

// ---------------- problem constants ----------------
#define D_NUMF   24
#define N_FREQ   16
#define D_EMB    32
#define D_IN     32
#define D_FEAT   776      // 24*32 + 8
#define DIM      512
#define D_OUT    10
#define NX       1024
#define NC       100000

// ---------------- tiling constants ----------------
#define ENC_M    32       // rows per encode block
#define ENC_DC   128      // d-chunk (output cols per pass)
#define ENC_KC   128      // k-chunk staged in smem
#define WS_STR   132      // padded stride for w chunk (conflict-free LDS.128)

#define XT       32       // x rows per nca block
#define CT       64       // candidate chunk
#define SPLITS   50
#define SPLIT_LEN 2000    // NC / SPLITS
#define CS_STR   516      // padded strides (516 mod 32 == 4 -> conflict-free)
#define XS_STR   516

// ---------------- device scratch (alloc-free) ----------------
__device__ float g_ce[NC * DIM];     // candidate embeddings
__device__ float g_cn[NC];           // candidate sq-norms
__device__ float g_xe[NX * DIM];     // x embeddings
__device__ float g_xn[NX];           // x sq-norms
__device__ float g_part[NX * SPLITS * (D_OUT + 1)];  // per-split partials: [l, num0..9]

// =====================================================================
// Kernel 1: encode (shared by candidates and x; block id selects source)
// =====================================================================
__global__ void __launch_bounds__(256, 1)
encode_kernel(const float* __restrict__ cx, const float* __restrict__ xx,
              const float* __restrict__ freq, const float* __restrict__ plr_w,
              const float* __restrict__ plr_b, const float* __restrict__ enc_w,
              const float* __restrict__ enc_b)
{
    extern __shared__ float smem[];
    float* feat = smem;                    // ENC_M * D_FEAT
    float* wbuf = smem + ENC_M * D_FEAT;   // ENC_DC * WS_STR

    __shared__ float s_freq[D_NUMF * N_FREQ];
    __shared__ float s_pw[D_EMB * 2 * N_FREQ];
    __shared__ float s_pb[D_EMB];

    const int tid = threadIdx.x;
    const int nCandBlocks = NC / ENC_M;          // 3125
    const bool isX = (blockIdx.x >= nCandBlocks);
    const float* __restrict__ src = isX ? xx : cx;
    float* __restrict__ dstE = isX ? g_xe : g_ce;
    float* __restrict__ dstN = isX ? g_xn : g_cn;
    const int rowBase = (isX ? (int)blockIdx.x - nCandBlocks : (int)blockIdx.x) * ENC_M;

    for (int i = tid; i < D_NUMF * N_FREQ; i += 256) s_freq[i] = freq[i];
    for (int i = tid; i < D_EMB * 2 * N_FREQ; i += 256) s_pw[i] = plr_w[i];
    if (tid < D_EMB) s_pb[tid] = plr_b[tid];
    __syncthreads();

    // ---- stage 1: PLR features into smem ----
    for (int p = tid; p < ENC_M * D_NUMF; p += 256) {
        const int row = p / D_NUMF;
        const int n   = p % D_NUMF;
        const float vn = src[(rowBase + row) * D_IN + n];
        float zc[N_FREQ], zs[N_FREQ];
#pragma unroll
        for (int f = 0; f < N_FREQ; f++) {
            float th = 6.283185307179586f * s_freq[n * N_FREQ + f] * vn;
            __sincosf(th, &zs[f], &zc[f]);
        }
        float* fr = feat + row * D_FEAT + n * D_EMB;
#pragma unroll 4
        for (int e = 0; e < D_EMB; e++) {
            float acc = s_pb[e];
#pragma unroll
            for (int f = 0; f < N_FREQ; f++) {
                acc += zc[f] * s_pw[e * 32 + f];
                acc += zs[f] * s_pw[e * 32 + 16 + f];
            }
            fr[e] = fmaxf(acc, 0.0f);
        }
    }
    if (tid < ENC_M * (D_IN - D_NUMF)) {
        const int row = tid / (D_IN - D_NUMF);
        const int c   = tid % (D_IN - D_NUMF);
        feat[row * D_FEAT + D_NUMF * D_EMB + c] = src[(rowBase + row) * D_IN + D_NUMF + c];
    }
    __syncthreads();

    // ---- stage 2: feat(32x776) @ enc_w^T(776x512) ----
    const int tm = tid >> 5;   // 0..7 -> rows 4*tm..4*tm+3
    const int tn = tid & 31;   // 0..31 -> cols tn + 32*j
    float rowsq[4] = {0.f, 0.f, 0.f, 0.f};

    for (int dc = 0; dc < DIM; dc += ENC_DC) {
        float acc[4][4];
#pragma unroll
        for (int j = 0; j < 4; j++) {
            const float b = enc_b[dc + tn + 32 * j];
#pragma unroll
            for (int i = 0; i < 4; i++) acc[i][j] = b;
        }

        for (int kb = 0; kb < D_FEAT; kb += ENC_KC) {
            const int kl = min(ENC_KC, D_FEAT - kb);   // 128 ... last = 8
            __syncthreads();
            // cooperative, coalesced stage of enc_w chunk
            const int tot4 = ENC_DC * (kl >> 2);
            for (int lin = tid; lin < tot4; lin += 256) {
                const int dd = lin / (kl >> 2);
                const int k4 = lin % (kl >> 2);
                const float4 wv = *(const float4*)(enc_w + (size_t)(dc + dd) * D_FEAT + kb + k4 * 4);
                *(float4*)(wbuf + dd * WS_STR + k4 * 4) = wv;
            }
            __syncthreads();

            for (int k = 0; k < kl; k += 4) {
                float4 fx[4], wv[4];
#pragma unroll
                for (int i = 0; i < 4; i++)
                    fx[i] = *(const float4*)(feat + (4 * tm + i) * D_FEAT + kb + k);
#pragma unroll
                for (int j = 0; j < 4; j++)
                    wv[j] = *(const float4*)(wbuf + (tn + 32 * j) * WS_STR + k);
#pragma unroll
                for (int i = 0; i < 4; i++) {
#pragma unroll
                    for (int j = 0; j < 4; j++) {
                        acc[i][j] += fx[i].x * wv[j].x;
                        acc[i][j] += fx[i].y * wv[j].y;
                        acc[i][j] += fx[i].z * wv[j].z;
                        acc[i][j] += fx[i].w * wv[j].w;
                    }
                }
            }
        }

#pragma unroll
        for (int i = 0; i < 4; i++) {
            const int row = rowBase + 4 * tm + i;
#pragma unroll
            for (int j = 0; j < 4; j++) {
                const int d = dc + tn + 32 * j;
                dstE[(size_t)row * DIM + d] = acc[i][j];
                rowsq[i] += acc[i][j] * acc[i][j];
            }
        }
    }

    // warp covers all 512 cols of its 4 rows -> warp reduce norms
#pragma unroll
    for (int i = 0; i < 4; i++) {
        float v = rowsq[i];
#pragma unroll
        for (int o = 16; o; o >>= 1) v += __shfl_xor_sync(0xffffffffu, v, o);
        if (tn == 0) dstN[rowBase + 4 * tm + i] = v;
    }
}

// =====================================================================
// Kernel 2: fused distance + softmax-accumulate + class aggregation
// grid: (NX/XT, SPLITS); x-tile fastest for L2 reuse of ce tiles
// =====================================================================
__global__ void __launch_bounds__(256, 1)
nca_kernel(const int* __restrict__ cy)
{
    extern __shared__ float smem[];
    float* xs = smem;                    // XT * XS_STR
    float* cs = smem + XT * XS_STR;      // CT * CS_STR
    __shared__ float s_cn[CT];
    __shared__ int   s_cy[CT];
    __shared__ float s_xn[XT];

    const int tid = threadIdx.x;
    const int tm = tid >> 5;   // rows 4*tm..4*tm+3
    const int tn = tid & 31;   // cols tn, tn+32
    const int xBase = blockIdx.x * XT;
    const int split = blockIdx.y;
    const int jBase0 = split * SPLIT_LEN;

    for (int lin = tid; lin < XT * (DIM / 4); lin += 256) {
        const int r  = lin / (DIM / 4);
        const int k4 = lin % (DIM / 4);
        *(float4*)(xs + r * XS_STR + k4 * 4) =
            *(const float4*)(g_xe + (size_t)(xBase + r) * DIM + k4 * 4);
    }
    if (tid < XT) s_xn[tid] = g_xn[xBase + tid];
    __syncthreads();

    float xn[4];
#pragma unroll
    for (int i = 0; i < 4; i++) xn[i] = s_xn[4 * tm + i];

    float l[4] = {0.f, 0.f, 0.f, 0.f};
    float num[4][D_OUT];
#pragma unroll
    for (int i = 0; i < 4; i++)
#pragma unroll
        for (int c = 0; c < D_OUT; c++) num[i][c] = 0.f;

    for (int jb = 0; jb < SPLIT_LEN; jb += CT) {
        __syncthreads();   // protect cs/s_cn/s_cy reuse
        const int nj = min(CT, SPLIT_LEN - jb);

        for (int lin = tid; lin < CT * (DIM / 4); lin += 256) {
            const int r  = lin / (DIM / 4);
            const int k4 = lin % (DIM / 4);
            float4 v = make_float4(0.f, 0.f, 0.f, 0.f);
            if (r < nj) v = *(const float4*)(g_ce + (size_t)(jBase0 + jb + r) * DIM + k4 * 4);
            *(float4*)(cs + r * CS_STR + k4 * 4) = v;
        }
        if (tid < CT) {
            const bool ok = tid < nj;
            s_cn[tid] = ok ? g_cn[jBase0 + jb + tid] : 0.f;
            s_cy[tid] = ok ? cy[jBase0 + jb + tid] : 0;
        }
        __syncthreads();

        float acc[4][2];
#pragma unroll
        for (int i = 0; i < 4; i++) { acc[i][0] = 0.f; acc[i][1] = 0.f; }

        for (int k = 0; k < DIM; k += 4) {
            float4 fx[4], fc[2];
#pragma unroll
            for (int i = 0; i < 4; i++)
                fx[i] = *(const float4*)(xs + (4 * tm + i) * XS_STR + k);
#pragma unroll
            for (int j = 0; j < 2; j++)
                fc[j] = *(const float4*)(cs + (tn + 32 * j) * CS_STR + k);
#pragma unroll
            for (int i = 0; i < 4; i++) {
#pragma unroll
                for (int j = 0; j < 2; j++) {
                    acc[i][j] += fx[i].x * fc[j].x;
                    acc[i][j] += fx[i].y * fc[j].y;
                    acc[i][j] += fx[i].z * fc[j].z;
                    acc[i][j] += fx[i].w * fc[j].w;
                }
            }
        }

        // epilogue: exp(-dist), class-scatter via predicated adds (no max needed:
        // scores <= 0 so exp in (4e-18, 1], fp32-safe)
#pragma unroll
        for (int j = 0; j < 2; j++) {
            const int col = tn + 32 * j;
            if (col < nj) {
                const float cn = s_cn[col];
                const int   y  = s_cy[col];
#pragma unroll
                for (int i = 0; i < 4; i++) {
                    const float sq = xn[i] + cn - 2.f * acc[i][j];
                    const float d  = sqrtf(fmaxf(sq, 1e-12f));
                    const float e  = __expf(-d);
                    l[i] += e;
#pragma unroll
                    for (int c = 0; c < D_OUT; c++)
                        num[i][c] += (y == c) ? e : 0.f;
                }
            }
        }
    }

    // warp-level sums (all lanes of a warp share the same 4 rows)
#pragma unroll
    for (int i = 0; i < 4; i++) {
        float v = l[i];
#pragma unroll
        for (int o = 16; o; o >>= 1) v += __shfl_xor_sync(0xffffffffu, v, o);
        l[i] = v;
#pragma unroll
        for (int c = 0; c < D_OUT; c++) {
            float u = num[i][c];
#pragma unroll
            for (int o = 16; o; o >>= 1) u += __shfl_xor_sync(0xffffffffu, u, o);
            num[i][c] = u;
        }
    }
    if (tn == 0) {
#pragma unroll
        for (int i = 0; i < 4; i++) {
            const int row = xBase + 4 * tm + i;
            float* P = g_part + ((size_t)row * SPLITS + split) * (D_OUT + 1);
            P[0] = l[i];
#pragma unroll
            for (int c = 0; c < D_OUT; c++) P[1 + c] = num[i][c];
        }
    }
}

// =====================================================================
// Kernel 3: reduce split partials and write log-probs
// =====================================================================
__global__ void finalize_kernel(float* __restrict__ out)
{
    const int row = blockIdx.x * blockDim.x + threadIdx.x;
    if (row >= NX) return;
    float l = 0.f;
    float num[D_OUT];
#pragma unroll
    for (int c = 0; c < D_OUT; c++) num[c] = 0.f;
    const float* P = g_part + (size_t)row * SPLITS * (D_OUT + 1);
    for (int s = 0; s < SPLITS; s++) {
        l += P[s * (D_OUT + 1)];
#pragma unroll
        for (int c = 0; c < D_OUT; c++) num[c] += P[s * (D_OUT + 1) + 1 + c];
    }
    const float inv = 1.0f / l;
#pragma unroll
    for (int c = 0; c < D_OUT; c++)
        out[row * D_OUT + c] = logf(num[c] * inv + 1e-7f);
}

// =====================================================================
extern "C" void kernel_launch(void* const* d_in, const int* in_sizes, int n_in,
                              void* d_out, int out_size)
{
    const float* x     = (const float*)d_in[0];
    const float* cx    = (const float*)d_in[1];
    const int*   cy    = (const int*)d_in[2];
    const float* freq  = (const float*)d_in[3];
    const float* plr_w = (const float*)d_in[4];
    const float* plr_b = (const float*)d_in[5];
    const float* enc_w = (const float*)d_in[6];
    const float* enc_b = (const float*)d_in[7];
    float* out = (float*)d_out;

    const size_t encSmem = (size_t)(ENC_M * D_FEAT + ENC_DC * WS_STR) * sizeof(float); // 166912
    const size_t ncaSmem = (size_t)(XT * XS_STR + CT * CS_STR) * sizeof(float);        // 198144
    cudaFuncSetAttribute(encode_kernel, cudaFuncAttributeMaxDynamicSharedMemorySize, (int)encSmem);
    cudaFuncSetAttribute(nca_kernel,    cudaFuncAttributeMaxDynamicSharedMemorySize, (int)ncaSmem);

    const int encBlocks = NC / ENC_M + NX / ENC_M;   // 3125 + 32
    encode_kernel<<<encBlocks, 256, encSmem>>>(cx, x, freq, plr_w, plr_b, enc_w, enc_b);

    dim3 g2(NX / XT, SPLITS);                         // (32, 50), x fastest for L2 reuse
    nca_kernel<<<g2, 256, ncaSmem>>>(cy);

    finalize_kernel<<<(NX + 255) / 256, 256>>>(out);
}

// round 6
// speedup vs baseline: 3.9166x; 3.8946x over previous
#include <cuda_runtime.h>
#include <cuda_bf16.h>
#include <stdint.h>
#include <math.h>

#define D_IN     32
#define KF       832            // padded feature dim (26*32)
#define KF2      (2*KF)         // [hi|lo] elements per feat row
#define DIM      512
#define D_OUT    10
#define NX       1024
#define NC       100000
#define NCPAD    102400         // 800 * 128
#define NROWS    (NCPAD + NX)   // 103424 = 808*128
#define NSPLIT   800            // candidate blocks of 128
#define TWO_PI   6.283185307179586f

// ---------------- device scratch (alloc-free) ----------------
__device__ __align__(16) __nv_bfloat16 g_fb[(size_t)NROWS * KF2];   // packed feats [hi832|lo832]
__device__ __align__(16) __nv_bfloat16 g_wb[(size_t)DIM * KF2];     // packed enc_w
__device__ __align__(16) __nv_bfloat16 g_emb[(size_t)NROWS * 1024]; // packed emb [hi512|lo512]
__device__ float g_nrm[NROWS];
__device__ float g_part[(size_t)NX * NSPLIT * D_OUT];

// ---------------- PTX helpers (all base-sm_103 legal) ----------------
__device__ __forceinline__ uint32_t smem_u32(const void* p) {
    uint32_t a;
    asm("{ .reg .u64 t; cvta.to.shared.u64 t, %1; cvt.u32.u64 %0, t; }" : "=r"(a) : "l"(p));
    return a;
}
__device__ __forceinline__ void ldsm4(uint32_t& r0, uint32_t& r1, uint32_t& r2, uint32_t& r3, uint32_t a) {
    asm volatile("ldmatrix.sync.aligned.m8n8.x4.shared.b16 {%0,%1,%2,%3}, [%4];"
                 : "=r"(r0), "=r"(r1), "=r"(r2), "=r"(r3) : "r"(a));
}
__device__ __forceinline__ void mma16816(float* c, const uint32_t* a, const uint32_t* b) {
    asm volatile("mma.sync.aligned.m16n8k16.row.col.f32.bf16.bf16.f32 "
                 "{%0,%1,%2,%3}, {%4,%5,%6,%7}, {%8,%9}, {%0,%1,%2,%3};"
                 : "+f"(c[0]), "+f"(c[1]), "+f"(c[2]), "+f"(c[3])
                 : "r"(a[0]), "r"(a[1]), "r"(a[2]), "r"(a[3]), "r"(b[0]), "r"(b[1]));
}
__device__ __forceinline__ void cp16(uint32_t dst, const void* src) {
    asm volatile("cp.async.ca.shared.global [%0], [%1], 16;" :: "r"(dst), "l"(src));
}
#define CP_COMMIT() asm volatile("cp.async.commit_group;" ::: "memory")
#define CP_WAIT1()  asm volatile("cp.async.wait_group 1;" ::: "memory")
#define CP_WAIT0()  asm volatile("cp.async.wait_group 0;" ::: "memory")

__device__ __forceinline__ uint32_t pack2(float a, float b, float* la, float* lb) {
    __nv_bfloat16 h0 = __float2bfloat16_rn(a), h1 = __float2bfloat16_rn(b);
    *la = a - __bfloat162float(h0);
    *lb = b - __bfloat162float(h1);
    return ((uint32_t)__bfloat16_as_ushort(h1) << 16) | (uint32_t)__bfloat16_as_ushort(h0);
}
__device__ __forceinline__ uint32_t pack2lo(float a, float b) {
    __nv_bfloat16 h0 = __float2bfloat16_rn(a), h1 = __float2bfloat16_rn(b);
    return ((uint32_t)__bfloat16_as_ushort(h1) << 16) | (uint32_t)__bfloat16_as_ushort(h0);
}

// smem stage layout per buffer (40960 B):
//   A: [ver][128 rows][40 elems pad] at 0 / 10240
//   B: same at 20480 / 30720
#define BUFB 40960

__device__ __forceinline__ void stageAB(uint32_t sbase, const char* gA, const char* gB,
                                        int strA, int strB, int halfA, int halfB, int tid)
{
#pragma unroll
    for (int it = 0; it < 8; it++) {
        const int e   = it * 256 + tid;
        const int isB = e >> 10;
        const int id  = e & 1023;
        const int r   = id >> 3;
        const int v   = (id >> 2) & 1;
        const int s   = id & 3;
        const char* g = isB ? gB : gA;
        const int str = isB ? strB : strA;
        const int hf  = isB ? halfB : halfA;
        cp16(sbase + isB * 20480 + v * 10240 + r * 80 + s * 16,
             g + (size_t)r * str + v * hf + s * 16);
    }
}

// warp microkernel: m16 (row wid*16) x n128, one 32-wide K chunk, 3-term hi/lo
__device__ __forceinline__ void gemm_step(uint32_t sbuf, float (*acc)[4], int wid, int lane)
{
    const uint32_t aoff = (uint32_t)(wid * 16 + (lane & 15)) * 80;
    const uint32_t boff = (uint32_t)((lane & 7) + ((lane >> 4) << 3)) * 80;
    const uint32_t kaa  = (uint32_t)((lane >> 4) << 3) * 2;
    const uint32_t kbb  = (uint32_t)(((lane >> 3) & 1) << 3) * 2;
#pragma unroll
    for (int ks = 0; ks < 2; ks++) {
        const uint32_t kc = ks * 32;
        uint32_t ah[4], al[4];
        ldsm4(ah[0], ah[1], ah[2], ah[3], sbuf + aoff + kaa + kc);
        ldsm4(al[0], al[1], al[2], al[3], sbuf + 10240 + aoff + kaa + kc);
        uint32_t bh[32], bl[32];
#pragma unroll
        for (int p = 0; p < 8; p++) {
            const uint32_t ba = sbuf + 20480 + boff + kbb + kc + p * 1280;
            ldsm4(bh[4*p], bh[4*p+1], bh[4*p+2], bh[4*p+3], ba);
            ldsm4(bl[4*p], bl[4*p+1], bl[4*p+2], bl[4*p+3], ba + 10240);
        }
#pragma unroll
        for (int t = 0; t < 16; t++) mma16816(acc[t], ah, &bh[2*t]);
#pragma unroll
        for (int t = 0; t < 16; t++) mma16816(acc[t], ah, &bl[2*t]);
#pragma unroll
        for (int t = 0; t < 16; t++) mma16816(acc[t], al, &bh[2*t]);
    }
}

// =====================================================================
// Kernel 1: feature generation -> packed [hi(832)|lo(832)] bf16 rows
// =====================================================================
__global__ void __launch_bounds__(256)
featgen_kernel(const float* __restrict__ cx, const float* __restrict__ xx,
               const float* __restrict__ freq, const float* __restrict__ plr_w,
               const float* __restrict__ plr_b)
{
    __shared__ float s_x[256 * 33];
    __shared__ float s_fr[384];
    __shared__ float s_pw[1024];
    __shared__ float s_pb[32];
    const int tid = threadIdx.x;
    const size_t rowBase = (size_t)blockIdx.x * 256;

    for (int i = tid; i < 384; i += 256) s_fr[i] = freq[i];
    for (int i = tid; i < 1024; i += 256) s_pw[i] = plr_w[i];
    if (tid < 32) s_pb[tid] = plr_b[tid];
    for (int i = tid; i < 256 * 32; i += 256) {
        const int r = i >> 5, k = i & 31;
        const size_t gr = rowBase + r;
        float v = 0.f;
        if (gr < NC) v = cx[gr * D_IN + k];
        else if (gr >= NCPAD) v = xx[(gr - NCPAD) * D_IN + k];
        s_x[r * 33 + k] = v;
    }
    __syncthreads();

    const float* xs = s_x + tid * 33;
    __nv_bfloat16* dst = g_fb + (rowBase + tid) * KF2;

    for (int n = 0; n < 24; n++) {
        const float v = xs[n];
        float cz[16], sz[16];
#pragma unroll
        for (int f = 0; f < 16; f++) {
            float ss, cc;
            __sincosf(TWO_PI * s_fr[n * 16 + f] * v, &ss, &cc);
            sz[f] = ss; cz[f] = cc;
        }
        float fv[32];
#pragma unroll 4
        for (int e = 0; e < 32; e++) {
            float acc = s_pb[e];
            const float* pw = s_pw + e * 32;
#pragma unroll
            for (int f = 0; f < 16; f++) {
                acc = fmaf(cz[f], pw[f], acc);
                acc = fmaf(sz[f], pw[16 + f], acc);
            }
            fv[e] = fmaxf(acc, 0.f);
        }
        uint32_t WH[16], WL[16];
#pragma unroll
        for (int q = 0; q < 16; q++) {
            float l0, l1;
            WH[q] = pack2(fv[2 * q], fv[2 * q + 1], &l0, &l1);
            WL[q] = pack2lo(l0, l1);
        }
        char* dh = (char*)dst + n * 64;
        char* dl = (char*)dst + KF * 2 + n * 64;
#pragma unroll
        for (int q = 0; q < 4; q++) {
            *(uint4*)(dh + q * 16) = make_uint4(WH[4*q], WH[4*q+1], WH[4*q+2], WH[4*q+3]);
            *(uint4*)(dl + q * 16) = make_uint4(WL[4*q], WL[4*q+1], WL[4*q+2], WL[4*q+3]);
        }
    }
#pragma unroll 8
    for (int k = 0; k < 64; k++) {     // cat tail 768..775 + zero pad to 832
        const float v = (k < 8) ? xs[24 + k] : 0.f;
        __nv_bfloat16 h = __float2bfloat16_rn(v);
        dst[768 + k]      = h;
        dst[KF + 768 + k] = __float2bfloat16_rn(v - __bfloat162float(h));
    }
}

// =====================================================================
// Kernel 2: pack enc_w -> [hi|lo]
// =====================================================================
__global__ void wprep_kernel(const float* __restrict__ enc_w)
{
    const int idx = blockIdx.x * 256 + threadIdx.x;
    if (idx >= DIM * KF) return;
    const int n = idx / KF, k = idx % KF;
    const float v = (k < 776) ? enc_w[n * 776 + k] : 0.f;
    __nv_bfloat16 h = __float2bfloat16_rn(v);
    g_wb[(size_t)n * KF2 + k]      = h;
    g_wb[(size_t)n * KF2 + KF + k] = __float2bfloat16_rn(v - __bfloat162float(h));
}

// =====================================================================
// Kernel 3: encode GEMM via mma.sync: 128 rows x 128 cols per block
// =====================================================================
__global__ void __launch_bounds__(256)
enc_mma_kernel(const float* __restrict__ enc_b)
{
    extern __shared__ char sm[];
    __shared__ float s_bias[128];
    const uint32_t sb = smem_u32(sm);
    const int tid = threadIdx.x, wid = tid >> 5, lane = tid & 31;
    const size_t rowBase = (size_t)blockIdx.x * 128;
    const int colBase = blockIdx.y * 128;
    if (tid < 128) s_bias[tid] = enc_b[colBase + tid];

    const char* gA = (const char*)(g_fb + rowBase * KF2);
    const char* gB = (const char*)(g_wb + (size_t)colBase * KF2);

    float acc[16][4];
#pragma unroll
    for (int t = 0; t < 16; t++)
#pragma unroll
        for (int u = 0; u < 4; u++) acc[t][u] = 0.f;

    stageAB(sb, gA, gB, KF2 * 2, KF2 * 2, KF * 2, KF * 2, tid);
    CP_COMMIT();
    for (int kb = 0; kb < 26; kb++) {
        if (kb + 1 < 26) {
            stageAB(sb + ((kb + 1) & 1) * BUFB, gA + (kb + 1) * 64, gB + (kb + 1) * 64,
                    KF2 * 2, KF2 * 2, KF * 2, KF * 2, tid);
            CP_COMMIT();
            CP_WAIT1();
        } else {
            CP_WAIT0();
        }
        __syncthreads();
        gemm_step(sb + (kb & 1) * BUFB, acc, wid, lane);
        __syncthreads();
    }

    // epilogue: bias + hi/lo pack -> g_emb
    const int g = lane >> 2, tig = lane & 3;
    const size_t r0 = rowBase + wid * 16 + g;
    const size_t r1 = r0 + 8;
#pragma unroll
    for (int nt = 0; nt < 16; nt++) {
        const int col = nt * 8 + tig * 2;
        const float b0 = s_bias[col], b1 = s_bias[col + 1];
        {
            float l0, l1;
            const uint32_t hi = pack2(acc[nt][0] + b0, acc[nt][1] + b1, &l0, &l1);
            const uint32_t lo = pack2lo(l0, l1);
            uint32_t* p = (uint32_t*)(g_emb + r0 * 1024 + colBase + col);
            p[0] = hi; p[256] = lo;
        }
        {
            float l0, l1;
            const uint32_t hi = pack2(acc[nt][2] + b0, acc[nt][3] + b1, &l0, &l1);
            const uint32_t lo = pack2lo(l0, l1);
            uint32_t* p = (uint32_t*)(g_emb + r1 * 1024 + colBase + col);
            p[0] = hi; p[256] = lo;
        }
    }
}

// =====================================================================
// Kernel 4: norms from packed embeddings (consistent with MMA operands)
// =====================================================================
__global__ void __launch_bounds__(256)
norm_kernel()
{
    const int w = (blockIdx.x * 256 + threadIdx.x) >> 5;
    const int lane = threadIdx.x & 31;
    if (w >= NROWS) return;
    const uint4* B = (const uint4*)(g_emb + (size_t)w * 1024);
    float s = 0.f;
#pragma unroll
    for (int h = 0; h < 2; h++) {
        const uint4 qh = B[lane + 32 * h];
        const uint4 ql = B[64 + lane + 32 * h];
        const uint32_t* a = (const uint32_t*)&qh;
        const uint32_t* b = (const uint32_t*)&ql;
#pragma unroll
        for (int i = 0; i < 4; i++) {
            const float2 hf = __bfloat1622float2(*(const __nv_bfloat162*)&a[i]);
            const float2 lf = __bfloat1622float2(*(const __nv_bfloat162*)&b[i]);
            const float v0 = hf.x + lf.x, v1 = hf.y + lf.y;
            s = fmaf(v0, v0, s);
            s = fmaf(v1, v1, s);
        }
    }
#pragma unroll
    for (int o = 16; o; o >>= 1) s += __shfl_xor_sync(0xffffffffu, s, o);
    if (lane == 0) g_nrm[w] = s;
}

// =====================================================================
// Kernel 5: NCA GEMM + distance/exp/class partials
// grid (NX/128, NCPAD/128): M = x rows, N = candidates
// =====================================================================
__global__ void __launch_bounds__(256)
nca_mma_kernel(const int* __restrict__ cy)
{
    extern __shared__ char sm[];
    __shared__ float s_cn[128];
    __shared__ int   s_cy[128];
    const uint32_t sb = smem_u32(sm);
    const int tid = threadIdx.x, wid = tid >> 5, lane = tid & 31;
    const int xBase = blockIdx.x * 128;
    const int cBase = blockIdx.y * 128;

    if (tid < 128) {
        const int j = cBase + tid;
        const bool ok = j < NC;
        s_cn[tid] = ok ? g_nrm[j] : 0.f;
        s_cy[tid] = ok ? cy[j] : 0;
    }

    const char* gA = (const char*)(g_emb + (size_t)(NCPAD + xBase) * 1024);
    const char* gB = (const char*)(g_emb + (size_t)cBase * 1024);

    float acc[16][4];
#pragma unroll
    for (int t = 0; t < 16; t++)
#pragma unroll
        for (int u = 0; u < 4; u++) acc[t][u] = 0.f;

    stageAB(sb, gA, gB, 2048, 2048, 1024, 1024, tid);
    CP_COMMIT();
    for (int kb = 0; kb < 16; kb++) {
        if (kb + 1 < 16) {
            stageAB(sb + ((kb + 1) & 1) * BUFB, gA + (kb + 1) * 64, gB + (kb + 1) * 64,
                    2048, 2048, 1024, 1024, tid);
            CP_COMMIT();
            CP_WAIT1();
        } else {
            CP_WAIT0();
        }
        __syncthreads();
        gemm_step(sb + (kb & 1) * BUFB, acc, wid, lane);
        __syncthreads();
    }

    // epilogue: distances -> exp -> class partials (scores <= 0, no max needed)
    const int g = lane >> 2, tig = lane & 3;
    const int xr0 = xBase + wid * 16 + g;
    const float xn0 = g_nrm[NCPAD + xr0];
    const float xn1 = g_nrm[NCPAD + xr0 + 8];
    float n0[D_OUT], n1[D_OUT];
#pragma unroll
    for (int c = 0; c < D_OUT; c++) { n0[c] = 0.f; n1[c] = 0.f; }

#pragma unroll
    for (int nt = 0; nt < 16; nt++) {
#pragma unroll
        for (int u = 0; u < 2; u++) {
            const int col = nt * 8 + tig * 2 + u;
            if (cBase + col < NC) {
                const float cn = s_cn[col];
                const int   y  = s_cy[col];
                const float sq0 = fmaxf(xn0 + cn - 2.f * acc[nt][u],     1e-12f);
                const float sq1 = fmaxf(xn1 + cn - 2.f * acc[nt][2 + u], 1e-12f);
                const float e0 = __expf(-sqrtf(sq0));
                const float e1 = __expf(-sqrtf(sq1));
#pragma unroll
                for (int c = 0; c < D_OUT; c++) {
                    n0[c] += (y == c) ? e0 : 0.f;
                    n1[c] += (y == c) ? e1 : 0.f;
                }
            }
        }
    }
#pragma unroll
    for (int c = 0; c < D_OUT; c++) {
        n0[c] += __shfl_xor_sync(0xffffffffu, n0[c], 1);
        n0[c] += __shfl_xor_sync(0xffffffffu, n0[c], 2);
        n1[c] += __shfl_xor_sync(0xffffffffu, n1[c], 1);
        n1[c] += __shfl_xor_sync(0xffffffffu, n1[c], 2);
    }
    if (tig == 0) {
        float* P0 = g_part + ((size_t)xr0 * NSPLIT + blockIdx.y) * D_OUT;
        float* P1 = g_part + ((size_t)(xr0 + 8) * NSPLIT + blockIdx.y) * D_OUT;
#pragma unroll
        for (int c = 0; c < D_OUT; c++) { P0[c] = n0[c]; P1[c] = n1[c]; }
    }
}

// =====================================================================
// Kernel 6: reduce partials -> log-probs (warp per x row, deterministic)
// =====================================================================
__global__ void __launch_bounds__(256)
finalize_kernel(float* __restrict__ out)
{
    const int w = (blockIdx.x * 256 + threadIdx.x) >> 5;
    const int lane = threadIdx.x & 31;
    if (w >= NX) return;
    const float* P = g_part + (size_t)w * NSPLIT * D_OUT;
    float n[D_OUT];
#pragma unroll
    for (int c = 0; c < D_OUT; c++) n[c] = 0.f;
    for (int s = lane; s < NSPLIT; s += 32) {
        const float* q = P + s * D_OUT;
#pragma unroll
        for (int c = 0; c < D_OUT; c++) n[c] += q[c];
    }
#pragma unroll
    for (int o = 16; o; o >>= 1)
#pragma unroll
        for (int c = 0; c < D_OUT; c++) n[c] += __shfl_xor_sync(0xffffffffu, n[c], o);
    if (lane == 0) {
        float l = 0.f;
#pragma unroll
        for (int c = 0; c < D_OUT; c++) l += n[c];
        const float inv = 1.0f / l;
#pragma unroll
        for (int c = 0; c < D_OUT; c++)
            out[w * D_OUT + c] = logf(n[c] * inv + 1e-7f);
    }
}

// =====================================================================
extern "C" void kernel_launch(void* const* d_in, const int* in_sizes, int n_in,
                              void* d_out, int out_size)
{
    const float* x     = (const float*)d_in[0];
    const float* cx    = (const float*)d_in[1];
    const int*   cy    = (const int*)d_in[2];
    const float* freq  = (const float*)d_in[3];
    const float* plr_w = (const float*)d_in[4];
    const float* plr_b = (const float*)d_in[5];
    const float* enc_w = (const float*)d_in[6];
    const float* enc_b = (const float*)d_in[7];
    float* out = (float*)d_out;

    const int dynSmem = 2 * BUFB;   // 81920
    cudaFuncSetAttribute(enc_mma_kernel, cudaFuncAttributeMaxDynamicSharedMemorySize, dynSmem);
    cudaFuncSetAttribute(nca_mma_kernel, cudaFuncAttributeMaxDynamicSharedMemorySize, dynSmem);

    featgen_kernel<<<NROWS / 256, 256>>>(cx, x, freq, plr_w, plr_b);
    wprep_kernel<<<(DIM * KF + 255) / 256, 256>>>(enc_w);
    enc_mma_kernel<<<dim3(NROWS / 128, DIM / 128), 256, dynSmem>>>(enc_b);
    norm_kernel<<<NROWS / 8, 256>>>();
    nca_mma_kernel<<<dim3(NX / 128, NCPAD / 128), 256, dynSmem>>>(cy);
    finalize_kernel<<<(NX * 32) / 256, 256>>>(out);
}

// round 7
// speedup vs baseline: 8.2464x; 2.1055x over previous
#include <cuda_runtime.h>
#include <cuda_fp16.h>
#include <stdint.h>
#include <math.h>

#define D_IN     32
#define KF       832            // padded feature dim (26*32)
#define DIM      512
#define D_OUT    10
#define NX       1024
#define NC       100000
#define NCPAD    102400         // 800 * 128
#define NROWS    (NCPAD + NX)   // 103424 = 808*128
#define NSPLIT   800            // candidate blocks of 128
#define TWO_PI   6.283185307179586f

// ---------------- device scratch (alloc-free) ----------------
__device__ __align__(16) __half g_fb[(size_t)NROWS * KF];   // fp16 feats
__device__ __align__(16) __half g_wb[(size_t)DIM * KF];     // fp16 enc_w
__device__ __align__(16) __half g_emb[(size_t)NROWS * DIM]; // fp16 embeddings
__device__ float g_nrm[NROWS];
__device__ float g_part[(size_t)NX * NSPLIT * D_OUT];

// ---------------- PTX helpers (base-sm_103 legal) ----------------
__device__ __forceinline__ uint32_t smem_u32(const void* p) {
    uint32_t a;
    asm("{ .reg .u64 t; cvta.to.shared.u64 t, %1; cvt.u32.u64 %0, t; }" : "=r"(a) : "l"(p));
    return a;
}
__device__ __forceinline__ void ldsm4(uint32_t& r0, uint32_t& r1, uint32_t& r2, uint32_t& r3, uint32_t a) {
    asm volatile("ldmatrix.sync.aligned.m8n8.x4.shared.b16 {%0,%1,%2,%3}, [%4];"
                 : "=r"(r0), "=r"(r1), "=r"(r2), "=r"(r3) : "r"(a));
}
__device__ __forceinline__ void mma16816(float* c, const uint32_t* a, const uint32_t* b) {
    asm volatile("mma.sync.aligned.m16n8k16.row.col.f32.f16.f16.f32 "
                 "{%0,%1,%2,%3}, {%4,%5,%6,%7}, {%8,%9}, {%0,%1,%2,%3};"
                 : "+f"(c[0]), "+f"(c[1]), "+f"(c[2]), "+f"(c[3])
                 : "r"(a[0]), "r"(a[1]), "r"(a[2]), "r"(a[3]), "r"(b[0]), "r"(b[1]));
}
__device__ __forceinline__ void cp16(uint32_t dst, const void* src) {
    asm volatile("cp.async.ca.shared.global [%0], [%1], 16;" :: "r"(dst), "l"(src));
}
#define CP_COMMIT() asm volatile("cp.async.commit_group;" ::: "memory")
#define CP_WAIT1()  asm volatile("cp.async.wait_group 1;" ::: "memory")
#define CP_WAIT0()  asm volatile("cp.async.wait_group 0;" ::: "memory")

__device__ __forceinline__ uint32_t h2pack(float a, float b) {
    __half2 h = __floats2half2_rn(a, b);
    return *(uint32_t*)&h;
}

// fast sincos on the FMA pipe: quadrant reduction via magic-number rounding,
// Taylor deg-9/8 on [-pi/4, pi/4] (abs err < 3e-8). Robust for |z| < 2^22.
__device__ __forceinline__ void fsincos(float z, float* s, float* c) {
    const float t  = z * 0.6366197723675814f;       // z * 2/pi
    const float qm = t + 12582912.0f;               // round-to-nearest magic
    const float q  = qm - 12582912.0f;
    const int   iq = (int)__float_as_uint(qm) & 3;  // quadrant from mantissa bits
    float r = fmaf(q, -1.57079637e+00f, z);         // Cody-Waite hi
    r = fmaf(q, 4.3711388e-08f, r);                 // Cody-Waite lo
    const float r2 = r * r;
    float ps = fmaf(r2, fmaf(r2, fmaf(r2, fmaf(r2, 2.7557319e-6f, -1.9841270e-4f),
                    8.3333333e-3f), -1.6666667e-1f), 1.0f) * r;
    float pc = fmaf(r2, fmaf(r2, fmaf(r2, fmaf(r2, 2.4801587e-5f, -1.3888889e-3f),
                    4.1666667e-2f), -5.0e-1f), 1.0f);
    float ss = (iq & 1) ? pc : ps;
    float cc = (iq & 1) ? ps : pc;
    if (iq & 2) ss = -ss;
    if ((iq + 1) & 2) cc = -cc;
    *s = ss; *c = cc;
}

// smem stage layout per buffer (20480 B): A 128 rows x 80B pad at 0, B at 10240
#define BUFB 20480

__device__ __forceinline__ void stageAB(uint32_t sbase, const char* gA, const char* gB,
                                        int strA, int strB, int tid)
{
#pragma unroll
    for (int it = 0; it < 4; it++) {
        const int e   = it * 256 + tid;
        const int isB = e >> 9;
        const int id  = e & 511;
        const int r   = id >> 2;
        const int sgl = id & 3;
        const char* g = isB ? gB : gA;
        const int str = isB ? strB : strA;
        cp16(sbase + isB * 10240 + r * 80 + sgl * 16, g + (size_t)r * str + sgl * 16);
    }
}

// warp microkernel: m16 x n128, one 32-wide K chunk, single fp16 term
__device__ __forceinline__ void gemm_step(uint32_t sbuf, float (*acc)[4], int wid, int lane)
{
    const uint32_t aoff = (uint32_t)(wid * 16 + (lane & 15)) * 80;
    const uint32_t boff = (uint32_t)((lane & 7) + ((lane >> 4) << 3)) * 80;
    const uint32_t kaa  = (uint32_t)((lane >> 4) & 1) * 16;
    const uint32_t kbb  = (uint32_t)((lane >> 3) & 1) * 16;
#pragma unroll
    for (int ks = 0; ks < 2; ks++) {
        const uint32_t kc = ks * 32;
        uint32_t ah[4];
        ldsm4(ah[0], ah[1], ah[2], ah[3], sbuf + aoff + kaa + kc);
        uint32_t bh[32];
#pragma unroll
        for (int p = 0; p < 8; p++)
            ldsm4(bh[4*p], bh[4*p+1], bh[4*p+2], bh[4*p+3],
                  sbuf + 10240 + boff + kbb + kc + p * 1280);
#pragma unroll
        for (int t = 0; t < 16; t++) mma16816(acc[t], ah, &bh[2*t]);
    }
}

// =====================================================================
// Kernel 1: feature generation -> fp16 feature rows (832 padded)
// =====================================================================
__global__ void __launch_bounds__(256)
featgen_kernel(const float* __restrict__ cx, const float* __restrict__ xx,
               const float* __restrict__ freq, const float* __restrict__ plr_w,
               const float* __restrict__ plr_b)
{
    __shared__ float s_x[256 * 33];
    __shared__ float s_fr[384];
    __shared__ float s_pw[1024];
    __shared__ float s_pb[32];
    const int tid = threadIdx.x;
    const size_t rowBase = (size_t)blockIdx.x * 256;

    for (int i = tid; i < 384; i += 256) s_fr[i] = freq[i];
    for (int i = tid; i < 1024; i += 256) s_pw[i] = plr_w[i];
    if (tid < 32) s_pb[tid] = plr_b[tid];
    for (int i = tid; i < 256 * 32; i += 256) {
        const int r = i >> 5, k = i & 31;
        const size_t gr = rowBase + r;
        float v = 0.f;
        if (gr < NC) v = cx[gr * D_IN + k];
        else if (gr >= NCPAD) v = xx[(gr - NCPAD) * D_IN + k];
        s_x[r * 33 + k] = v;
    }
    __syncthreads();

    const float* xs = s_x + tid * 33;
    __half* dst = g_fb + (rowBase + tid) * KF;

    for (int n = 0; n < 24; n++) {
        const float v = xs[n];
        float cz[16], sz[16];
#pragma unroll
        for (int f = 0; f < 16; f++)
            fsincos(TWO_PI * s_fr[n * 16 + f] * v, &sz[f], &cz[f]);
        uint32_t W[16];
#pragma unroll 4
        for (int e2 = 0; e2 < 16; e2++) {
            float a0 = s_pb[2 * e2], a1 = s_pb[2 * e2 + 1];
            const float* pw0 = s_pw + (2 * e2) * 32;
            const float* pw1 = pw0 + 32;
#pragma unroll
            for (int f = 0; f < 16; f++) {
                a0 = fmaf(cz[f], pw0[f], a0);
                a0 = fmaf(sz[f], pw0[16 + f], a0);
                a1 = fmaf(cz[f], pw1[f], a1);
                a1 = fmaf(sz[f], pw1[16 + f], a1);
            }
            W[e2] = h2pack(fmaxf(a0, 0.f), fmaxf(a1, 0.f));
        }
        uint4* dq = (uint4*)((char*)dst + n * 64);
#pragma unroll
        for (int q = 0; q < 4; q++)
            dq[q] = make_uint4(W[4*q], W[4*q+1], W[4*q+2], W[4*q+3]);
    }
#pragma unroll 8
    for (int k = 0; k < 64; k++)   // cat tail 768..775 + zero pad to 832
        dst[768 + k] = __float2half_rn((k < 8) ? xs[24 + k] : 0.f);
}

// =====================================================================
// Kernel 2: pack enc_w -> fp16
// =====================================================================
__global__ void wprep_kernel(const float* __restrict__ enc_w)
{
    const int idx = blockIdx.x * 256 + threadIdx.x;
    if (idx >= DIM * KF) return;
    const int n = idx / KF, k = idx % KF;
    g_wb[(size_t)n * KF + k] = __float2half_rn((k < 776) ? enc_w[n * 776 + k] : 0.f);
}

// =====================================================================
// Kernel 3: encode GEMM via mma.sync: 128 rows x 128 cols per block
// =====================================================================
__global__ void __launch_bounds__(256)
enc_mma_kernel(const float* __restrict__ enc_b)
{
    extern __shared__ char sm[];
    __shared__ float s_bias[128];
    const uint32_t sb = smem_u32(sm);
    const int tid = threadIdx.x, wid = tid >> 5, lane = tid & 31;
    const size_t rowBase = (size_t)blockIdx.x * 128;
    const int colBase = blockIdx.y * 128;
    if (tid < 128) s_bias[tid] = enc_b[colBase + tid];

    const char* gA = (const char*)(g_fb + rowBase * KF);
    const char* gB = (const char*)(g_wb + (size_t)colBase * KF);
    const int str = KF * 2;   // 1664 B

    float acc[16][4];
#pragma unroll
    for (int t = 0; t < 16; t++)
#pragma unroll
        for (int u = 0; u < 4; u++) acc[t][u] = 0.f;

    stageAB(sb, gA, gB, str, str, tid);
    CP_COMMIT();
    for (int kb = 0; kb < 26; kb++) {
        if (kb + 1 < 26) {
            stageAB(sb + ((kb + 1) & 1) * BUFB, gA + (kb + 1) * 64, gB + (kb + 1) * 64,
                    str, str, tid);
            CP_COMMIT();
            CP_WAIT1();
        } else {
            CP_WAIT0();
        }
        __syncthreads();
        gemm_step(sb + (kb & 1) * BUFB, acc, wid, lane);
        __syncthreads();
    }

    // epilogue: bias + fp16 store
    const int g = lane >> 2, tig = lane & 3;
    const size_t r0 = rowBase + wid * 16 + g;
    const size_t r1 = r0 + 8;
#pragma unroll
    for (int nt = 0; nt < 16; nt++) {
        const int col = nt * 8 + tig * 2;
        const float b0 = s_bias[col], b1 = s_bias[col + 1];
        *(uint32_t*)(g_emb + r0 * DIM + colBase + col) = h2pack(acc[nt][0] + b0, acc[nt][1] + b1);
        *(uint32_t*)(g_emb + r1 * DIM + colBase + col) = h2pack(acc[nt][2] + b0, acc[nt][3] + b1);
    }
}

// =====================================================================
// Kernel 4: norms from fp16 embeddings (consistent with MMA operands)
// =====================================================================
__global__ void __launch_bounds__(256)
norm_kernel()
{
    const int w = (blockIdx.x * 256 + threadIdx.x) >> 5;
    const int lane = threadIdx.x & 31;
    if (w >= NROWS) return;
    const uint4* B = (const uint4*)(g_emb + (size_t)w * DIM);
    float s = 0.f;
#pragma unroll
    for (int h = 0; h < 2; h++) {
        const uint4 q = B[lane + 32 * h];
        const uint32_t* a = (const uint32_t*)&q;
#pragma unroll
        for (int i = 0; i < 4; i++) {
            const float2 f = __half22float2(*(const __half2*)&a[i]);
            s = fmaf(f.x, f.x, s);
            s = fmaf(f.y, f.y, s);
        }
    }
#pragma unroll
    for (int o = 16; o; o >>= 1) s += __shfl_xor_sync(0xffffffffu, s, o);
    if (lane == 0) g_nrm[w] = s;
}

// =====================================================================
// Kernel 5: NCA GEMM + distance/exp/class partials
// =====================================================================
__global__ void __launch_bounds__(256)
nca_mma_kernel(const int* __restrict__ cy)
{
    extern __shared__ char sm[];
    __shared__ float s_cn[128];
    __shared__ int   s_cy[128];
    const uint32_t sb = smem_u32(sm);
    const int tid = threadIdx.x, wid = tid >> 5, lane = tid & 31;
    const int xBase = blockIdx.x * 128;
    const int cBase = blockIdx.y * 128;

    if (tid < 128) {
        const int j = cBase + tid;
        const bool ok = j < NC;
        s_cn[tid] = ok ? g_nrm[j] : 0.f;
        s_cy[tid] = ok ? cy[j] : 0;
    }

    const char* gA = (const char*)(g_emb + (size_t)(NCPAD + xBase) * DIM);
    const char* gB = (const char*)(g_emb + (size_t)cBase * DIM);
    const int str = DIM * 2;   // 1024 B

    float acc[16][4];
#pragma unroll
    for (int t = 0; t < 16; t++)
#pragma unroll
        for (int u = 0; u < 4; u++) acc[t][u] = 0.f;

    stageAB(sb, gA, gB, str, str, tid);
    CP_COMMIT();
    for (int kb = 0; kb < 16; kb++) {
        if (kb + 1 < 16) {
            stageAB(sb + ((kb + 1) & 1) * BUFB, gA + (kb + 1) * 64, gB + (kb + 1) * 64,
                    str, str, tid);
            CP_COMMIT();
            CP_WAIT1();
        } else {
            CP_WAIT0();
        }
        __syncthreads();
        gemm_step(sb + (kb & 1) * BUFB, acc, wid, lane);
        __syncthreads();
    }

    // epilogue: distances -> exp -> class partials (scores <= 0, no max needed)
    const int g = lane >> 2, tig = lane & 3;
    const int xr0 = xBase + wid * 16 + g;
    const float xn0 = g_nrm[NCPAD + xr0];
    const float xn1 = g_nrm[NCPAD + xr0 + 8];
    float n0[D_OUT], n1[D_OUT];
#pragma unroll
    for (int c = 0; c < D_OUT; c++) { n0[c] = 0.f; n1[c] = 0.f; }

#pragma unroll
    for (int nt = 0; nt < 16; nt++) {
#pragma unroll
        for (int u = 0; u < 2; u++) {
            const int col = nt * 8 + tig * 2 + u;
            if (cBase + col < NC) {
                const float cn = s_cn[col];
                const int   y  = s_cy[col];
                const float sq0 = fmaxf(xn0 + cn - 2.f * acc[nt][u],     1e-12f);
                const float sq1 = fmaxf(xn1 + cn - 2.f * acc[nt][2 + u], 1e-12f);
                const float e0 = __expf(-sqrtf(sq0));
                const float e1 = __expf(-sqrtf(sq1));
#pragma unroll
                for (int c = 0; c < D_OUT; c++) {
                    n0[c] += (y == c) ? e0 : 0.f;
                    n1[c] += (y == c) ? e1 : 0.f;
                }
            }
        }
    }
#pragma unroll
    for (int c = 0; c < D_OUT; c++) {
        n0[c] += __shfl_xor_sync(0xffffffffu, n0[c], 1);
        n0[c] += __shfl_xor_sync(0xffffffffu, n0[c], 2);
        n1[c] += __shfl_xor_sync(0xffffffffu, n1[c], 1);
        n1[c] += __shfl_xor_sync(0xffffffffu, n1[c], 2);
    }
    if (tig == 0) {
        float* P0 = g_part + ((size_t)xr0 * NSPLIT + blockIdx.y) * D_OUT;
        float* P1 = g_part + ((size_t)(xr0 + 8) * NSPLIT + blockIdx.y) * D_OUT;
#pragma unroll
        for (int c = 0; c < D_OUT; c++) { P0[c] = n0[c]; P1[c] = n1[c]; }
    }
}

// =====================================================================
// Kernel 6: reduce partials -> log-probs (warp per x row, deterministic)
// =====================================================================
__global__ void __launch_bounds__(256)
finalize_kernel(float* __restrict__ out)
{
    const int w = (blockIdx.x * 256 + threadIdx.x) >> 5;
    const int lane = threadIdx.x & 31;
    if (w >= NX) return;
    const float* P = g_part + (size_t)w * NSPLIT * D_OUT;
    float n[D_OUT];
#pragma unroll
    for (int c = 0; c < D_OUT; c++) n[c] = 0.f;
    for (int s = lane; s < NSPLIT; s += 32) {
        const float* q = P + s * D_OUT;
#pragma unroll
        for (int c = 0; c < D_OUT; c++) n[c] += q[c];
    }
#pragma unroll
    for (int o = 16; o; o >>= 1)
#pragma unroll
        for (int c = 0; c < D_OUT; c++) n[c] += __shfl_xor_sync(0xffffffffu, n[c], o);
    if (lane == 0) {
        float l = 0.f;
#pragma unroll
        for (int c = 0; c < D_OUT; c++) l += n[c];
        const float inv = 1.0f / l;
#pragma unroll
        for (int c = 0; c < D_OUT; c++)
            out[w * D_OUT + c] = logf(n[c] * inv + 1e-7f);
    }
}

// =====================================================================
extern "C" void kernel_launch(void* const* d_in, const int* in_sizes, int n_in,
                              void* d_out, int out_size)
{
    const float* x     = (const float*)d_in[0];
    const float* cx    = (const float*)d_in[1];
    const int*   cy    = (const int*)d_in[2];
    const float* freq  = (const float*)d_in[3];
    const float* plr_w = (const float*)d_in[4];
    const float* plr_b = (const float*)d_in[5];
    const float* enc_w = (const float*)d_in[6];
    const float* enc_b = (const float*)d_in[7];
    float* out = (float*)d_out;

    const int dynSmem = 2 * BUFB;   // 40960
    cudaFuncSetAttribute(enc_mma_kernel, cudaFuncAttributeMaxDynamicSharedMemorySize, dynSmem);
    cudaFuncSetAttribute(nca_mma_kernel, cudaFuncAttributeMaxDynamicSharedMemorySize, dynSmem);

    featgen_kernel<<<NROWS / 256, 256>>>(cx, x, freq, plr_w, plr_b);
    wprep_kernel<<<(DIM * KF + 255) / 256, 256>>>(enc_w);
    enc_mma_kernel<<<dim3(NROWS / 128, DIM / 128), 256, dynSmem>>>(enc_b);
    norm_kernel<<<NROWS / 8, 256>>>();
    nca_mma_kernel<<<dim3(NX / 128, NCPAD / 128), 256, dynSmem>>>(cy);
    finalize_kernel<<<(NX * 32) / 256, 256>>>(out);
}